// round 8
// baseline (speedup 1.0000x reference)
#include <cuda_runtime.h>
#include <cuda_fp16.h>
#include <cstdint>

// ============================================================================
// out = LayerNorm(relu(x @ (m*W_v + (1-m)*W_r)))   [attention path is identity:
// softmax rows sum to 1 and the reference einsum contracts the softmax axis]
//   x: [131072, 256] f32,  W: [256, 512] f32,  out: [131072, 512] f32
// R8: 2 CTAs/SM for cross-CTA overlap (the profile shows latency-bound, no
// saturated pipe, occ 24% with one fat CTA). BM=32, NT=256, regs<=128,
// smem 80KB/CTA. fp16 mma.sync (rel_err ~3.5e-4), KC=32 double-buffered B.
// ============================================================================

static constexpr int K_DIM = 256;
static constexpr int N_DIM = 512;
static constexpr int BM    = 32;
static constexpr int KC    = 32;
static constexpr int NCH   = K_DIM / KC;   // 8
static constexpr int M_TOT = 2048 * 64;    // 131072
static constexpr int NT    = 256;          // 8 warps, each: 32 rows x 64 cols

// SMEM layout (bytes)
static constexpr int SM_B  = 0;            // 2 stages x 32 KB (packed 2 n-rows / 128B line)
static constexpr int SM_A  = 65536;        // 2 stages x 4 KB (32 rows x 128B, 64B used)
static constexpr int SM_GB = 73728;        // gamma[512]+beta[512] f32 = 4 KB
static constexpr int SM_PS = 77824;        // psum[32][8]+psq[32][8]+stats[32][2] = 2304
static constexpr int SMEM_TOTAL = 80128;

// Pre-swizzled fp16 B chunk images (exact smem stage byte layout):
// off(n, kk) = swz((n>>1)*128 + (n&1)*64 + kk*2), kk = k % 32, chunk = k / 32.
__device__ __align__(16) unsigned char g_Bimg[NCH][32768];

// ---------------------------------------------------------------------------
__device__ __forceinline__ uint32_t smem_u32(const void* p) {
    uint32_t r;
    asm("{ .reg .u64 t; cvta.to.shared.u64 t, %1; cvt.u32.u64 %0, t; }" : "=r"(r) : "l"(p));
    return r;
}
__host__ __device__ __forceinline__ uint32_t swz(uint32_t o) { return o ^ ((o >> 3) & 0x70); }

__device__ __forceinline__ void cp16(uint32_t d, const void* s) {
    asm volatile("cp.async.cg.shared.global [%0], [%1], 16;" :: "r"(d), "l"(s));
}
__device__ __forceinline__ void cp_commit() { asm volatile("cp.async.commit_group;"); }
__device__ __forceinline__ void cp_wait0()  { asm volatile("cp.async.wait_group 0;"); }

__device__ __forceinline__ void ldsm4(uint32_t* r, uint32_t a) {
    asm volatile("ldmatrix.sync.aligned.m8n8.x4.shared.b16 {%0,%1,%2,%3}, [%4];"
                 : "=r"(r[0]), "=r"(r[1]), "=r"(r[2]), "=r"(r[3]) : "r"(a));
}
__device__ __forceinline__ void hmma(float* c, const uint32_t* a, const uint32_t* b) {
    asm volatile("mma.sync.aligned.m16n8k16.row.col.f32.f16.f16.f32 "
                 "{%0,%1,%2,%3},{%4,%5,%6,%7},{%8,%9},{%0,%1,%2,%3};"
                 : "+f"(c[0]), "+f"(c[1]), "+f"(c[2]), "+f"(c[3])
                 : "r"(a[0]), "r"(a[1]), "r"(a[2]), "r"(a[3]), "r"(b[0]), "r"(b[1]));
}

// ---------------------------------------------------------------------------
// Prep: W_c = m*W_v + (1-m)*W_r -> fp16, pre-swizzled packed chunk images.
// ---------------------------------------------------------------------------
__global__ void prep_kernel(const float* __restrict__ Wv, const float* __restrict__ Wr,
                            const float* __restrict__ mix) {
    int gid = blockIdx.x * blockDim.x + threadIdx.x;
    if (gid >= K_DIM * N_DIM) return;
    int n = gid & 511;
    int k = gid >> 9;
    float m = 1.0f / (1.0f + expf(-mix[0]));
    float w = m * Wv[k * N_DIM + n] + (1.0f - m) * Wr[k * N_DIM + n];
    int c  = k >> 5;
    int kk = k & 31;
    uint32_t off = swz((uint32_t)((n >> 1) * 128 + (n & 1) * 64 + kk * 2));
    *(__half*)(&g_Bimg[c][off]) = __float2half(w);
}

// ---------------------------------------------------------------------------
// Fused GEMM (fp16 mma.sync) + relu + full-width LayerNorm(512)
// One CTA = 32 rows x 512 cols; 2 CTAs resident per SM.
// ---------------------------------------------------------------------------
__global__ void __launch_bounds__(NT, 2)
gemm_ln_kernel(const float* __restrict__ x, const float* __restrict__ gamma,
               const float* __restrict__ beta, float* __restrict__ out) {
    extern __shared__ char smem[];
    const uint32_t sb = smem_u32(smem);
    const int tid  = threadIdx.x;
    const int warp = tid >> 5;   // 0..7: 64-col slice; every warp covers all 32 rows
    const int lane = tid & 31;
    const int wn   = warp;

    const size_t m0 = (size_t)blockIdx.x * BM;

    // gamma/beta into smem
    {
        float* gsh = (float*)(smem + SM_GB);
        for (int i = tid; i < N_DIM; i += NT) {
            gsh[i]         = gamma[i];
            gsh[N_DIM + i] = beta[i];
        }
    }

    // per-lane ldmatrix base offsets (KC=32 packed layouts, verified R4/R6)
    const uint32_t arow = (uint32_t)((lane & 15) * 128 + (lane >> 4) * 16);  // + mt*2048
    const int nb = wn * 64 + ((lane >> 4) & 1) * 8 + (lane & 7);
    const uint32_t brow = (uint32_t)((nb >> 1) * 128 + (nb & 1) * 64 + ((lane >> 3) & 1) * 16);

    float acc[2][8][4];
    #pragma unroll
    for (int mt = 0; mt < 2; mt++)
        #pragma unroll
        for (int nt = 0; nt < 8; nt++)
            #pragma unroll
            for (int i = 0; i < 4; i++) acc[mt][nt][i] = 0.0f;

    // A indexing: chunk = 32 rows x 32 f32 = 256 float4; 1 per thread
    const int ar = tid >> 3;              // 0..31
    const int as = tid & 7;               // 0..7
    const uint32_t aso = swz((uint32_t)(ar * 128 + as * 8));
    const float* xrow = x + (m0 + ar) * K_DIM + as * 4;

    // ---- prologue: B chunk0 cp.async, A chunk0 STS, A chunk1 regs ----
    #pragma unroll
    for (int i = 0; i < 8; i++) {
        int j = tid + i * NT;              // 0..2047
        cp16(sb + SM_B + j * 16, &g_Bimg[0][j * 16]);
    }
    cp_commit();
    {
        float4 v = *(const float4*)(xrow);
        __half2 h01 = __floats2half2_rn(v.x, v.y);
        __half2 h23 = __floats2half2_rn(v.z, v.w);
        *(uint2*)(smem + SM_A + aso) = make_uint2(*(uint32_t*)&h01, *(uint32_t*)&h23);
    }
    float4 av = *(const float4*)(xrow + KC);

    #pragma unroll
    for (int c = 0; c < NCH; c++) {
        const int buf = c & 1;
        cp_wait0();
        __syncthreads();

        if (c < NCH - 1) {
            const int nbuf = buf ^ 1;
            // STS A chunk c+1
            __half2 h01 = __floats2half2_rn(av.x, av.y);
            __half2 h23 = __floats2half2_rn(av.z, av.w);
            *(uint2*)(smem + SM_A + nbuf * 4096 + aso) =
                make_uint2(*(uint32_t*)&h01, *(uint32_t*)&h23);
            // LDG A chunk c+2
            if (c < NCH - 2) av = *(const float4*)(xrow + (c + 2) * KC);
            // B chunk c+1 cp.async (overlaps MMA below)
            #pragma unroll
            for (int i = 0; i < 8; i++) {
                int j = tid + i * NT;
                cp16(sb + SM_B + nbuf * 32768 + j * 16, &g_Bimg[c + 1][j * 16]);
            }
            cp_commit();
        }

        // ---- MMA on chunk c: 2 k-steps ----
        const uint32_t Ab = sb + SM_A + buf * 4096;
        const uint32_t Bb = sb + SM_B + buf * 32768;
        uint32_t af[2][2][4];
        #pragma unroll
        for (int mt = 0; mt < 2; mt++)
            ldsm4(af[0][mt], Ab + swz(arow + mt * 2048));
        #pragma unroll
        for (int ks = 0; ks < 2; ks++) {
            if (ks == 0)
                #pragma unroll
                for (int mt = 0; mt < 2; mt++)
                    ldsm4(af[1][mt], Ab + swz(arow + mt * 2048 + 32));
            #pragma unroll
            for (int bt = 0; bt < 4; bt++) {
                uint32_t bh[4];
                ldsm4(bh, Bb + swz(brow + bt * 1024 + ks * 32));
                #pragma unroll
                for (int mt = 0; mt < 2; mt++) {
                    hmma(acc[mt][2 * bt],     af[ks][mt], &bh[0]);
                    hmma(acc[mt][2 * bt + 1], af[ks][mt], &bh[2]);
                }
            }
        }
    }

    // ------------------- Epilogue: relu + LayerNorm(512) -------------------
    float* psum  = (float*)(smem + SM_PS);   // [32][8]
    float* psq   = psum + 256;               // [32][8]
    float* stats = psq + 256;                // [32][2]

    #pragma unroll
    for (int mt = 0; mt < 2; mt++) {
        #pragma unroll
        for (int half = 0; half < 2; half++) {
            float s = 0.0f, q = 0.0f;
            #pragma unroll
            for (int nt = 0; nt < 8; nt++) {
                float v0 = fmaxf(acc[mt][nt][half * 2 + 0], 0.0f);
                float v1 = fmaxf(acc[mt][nt][half * 2 + 1], 0.0f);
                s += v0 + v1;
                q += v0 * v0 + v1 * v1;
            }
            s += __shfl_xor_sync(0xFFFFFFFFu, s, 1);
            q += __shfl_xor_sync(0xFFFFFFFFu, q, 1);
            s += __shfl_xor_sync(0xFFFFFFFFu, s, 2);
            q += __shfl_xor_sync(0xFFFFFFFFu, q, 2);
            if ((lane & 3) == 0) {
                int r = mt * 16 + (lane >> 2) + half * 8;   // 0..31
                psum[r * 8 + wn] = s;
                psq[r * 8 + wn]  = q;
            }
        }
    }
    __syncthreads();
    if (tid < BM) {
        float st = 0.0f, qt = 0.0f;
        #pragma unroll
        for (int i = 0; i < 8; i++) { st += psum[tid * 8 + i]; qt += psq[tid * 8 + i]; }
        float mean = st * (1.0f / 512.0f);
        float var  = qt * (1.0f / 512.0f) - mean * mean;
        stats[tid * 2]     = mean;
        stats[tid * 2 + 1] = rsqrtf(var + 1e-5f);
    }
    __syncthreads();

    const float* gsh = (const float*)(smem + SM_GB);
    const float* bsh = gsh + N_DIM;
    #pragma unroll
    for (int mt = 0; mt < 2; mt++) {
        #pragma unroll
        for (int half = 0; half < 2; half++) {
            int r = mt * 16 + (lane >> 2) + half * 8;
            float mean = stats[r * 2];
            float rstd = stats[r * 2 + 1];
            float* orow = out + (size_t)(m0 + r) * N_DIM;
            #pragma unroll
            for (int nt = 0; nt < 8; nt++) {
                int col = wn * 64 + nt * 8 + (lane & 3) * 2;
                float2 o;
                o.x = (fmaxf(acc[mt][nt][half * 2 + 0], 0.0f) - mean) * rstd * gsh[col]     + bsh[col];
                o.y = (fmaxf(acc[mt][nt][half * 2 + 1], 0.0f) - mean) * rstd * gsh[col + 1] + bsh[col + 1];
                *(float2*)(orow + col) = o;
            }
        }
    }
}

// ---------------------------------------------------------------------------
// Host launcher. Inputs: x, W_q, W_k, W_v, W_r, mix, gamma, beta
// ---------------------------------------------------------------------------
extern "C" void kernel_launch(void* const* d_in, const int* in_sizes, int n_in,
                              void* d_out, int out_size) {
    const float* x     = (const float*)d_in[0];
    const float* Wv    = (const float*)d_in[3];
    const float* Wr    = (const float*)d_in[4];
    const float* mix   = (const float*)d_in[5];
    const float* gamma = (const float*)d_in[6];
    const float* beta  = (const float*)d_in[7];
    float* out = (float*)d_out;

    cudaFuncSetAttribute(gemm_ln_kernel, cudaFuncAttributeMaxDynamicSharedMemorySize, SMEM_TOTAL);

    prep_kernel<<<(K_DIM * N_DIM + 255) / 256, 256>>>(Wv, Wr, mix);
    gemm_ln_kernel<<<M_TOT / BM, NT, SMEM_TOTAL>>>(x, gamma, beta, out);
}

// round 9
// speedup vs baseline: 1.0756x; 1.0756x over previous
#include <cuda_runtime.h>
#include <cuda_fp16.h>
#include <cstdint>

// ============================================================================
// out = LayerNorm(relu(x @ (m*W_v + (1-m)*W_r)))   [attention path is identity:
// softmax rows sum to 1 and the reference einsum contracts the softmax axis]
//   x: [131072, 256] f32,  W: [256, 512] f32,  out: [131072, 512] f32
// R9: fp16 mma.sync with BIG warp tiles (64x64 -> LDSM:HMMA = 1:4; fragment
// reuse is the variable that tracks tensor% across all prior rounds).
// 8 warps, NT=256, CTA = 64 rows x 512 cols, KC=64 double-buffered.
// ============================================================================

static constexpr int K_DIM = 256;
static constexpr int N_DIM = 512;
static constexpr int BM    = 64;
static constexpr int KC    = 64;
static constexpr int NCH   = K_DIM / KC;   // 4
static constexpr int M_TOT = 2048 * 64;    // 131072
static constexpr int NT    = 256;          // 8 warps; warp w covers all 64 rows x cols [w*64, w*64+64)

// SMEM layout (bytes)
static constexpr int SM_B  = 0;            // 2 stages x 64 KB (512 n-rows x 128B)
static constexpr int SM_A  = 131072;       // 2 stages x 8 KB (64 rows x 128B)
static constexpr int SM_GB = 147456;       // gamma[512]+beta[512] f32 = 4 KB
static constexpr int SM_PS = 151552;       // psum[64][8]+psq[64][8]+stats[64][2] = 4608
static constexpr int SMEM_TOTAL = 156160;

// Pre-swizzled fp16 B chunk images: off(n,kk) = swz(n*128 + kk*2), kk = k%64.
__device__ __align__(16) unsigned char g_Bimg[NCH][65536];

// ---------------------------------------------------------------------------
__device__ __forceinline__ uint32_t smem_u32(const void* p) {
    uint32_t r;
    asm("{ .reg .u64 t; cvta.to.shared.u64 t, %1; cvt.u32.u64 %0, t; }" : "=r"(r) : "l"(p));
    return r;
}
__host__ __device__ __forceinline__ uint32_t swz(uint32_t o) { return o ^ ((o >> 3) & 0x70); }

__device__ __forceinline__ void cp16(uint32_t d, const void* s) {
    asm volatile("cp.async.cg.shared.global [%0], [%1], 16;" :: "r"(d), "l"(s));
}
__device__ __forceinline__ void cp_commit() { asm volatile("cp.async.commit_group;"); }
__device__ __forceinline__ void cp_wait0()  { asm volatile("cp.async.wait_group 0;"); }

__device__ __forceinline__ void ldsm4(uint32_t* r, uint32_t a) {
    asm volatile("ldmatrix.sync.aligned.m8n8.x4.shared.b16 {%0,%1,%2,%3}, [%4];"
                 : "=r"(r[0]), "=r"(r[1]), "=r"(r[2]), "=r"(r[3]) : "r"(a));
}
__device__ __forceinline__ void hmma(float* c, const uint32_t* a, const uint32_t* b) {
    asm volatile("mma.sync.aligned.m16n8k16.row.col.f32.f16.f16.f32 "
                 "{%0,%1,%2,%3},{%4,%5,%6,%7},{%8,%9},{%0,%1,%2,%3};"
                 : "+f"(c[0]), "+f"(c[1]), "+f"(c[2]), "+f"(c[3])
                 : "r"(a[0]), "r"(a[1]), "r"(a[2]), "r"(a[3]), "r"(b[0]), "r"(b[1]));
}

// ---------------------------------------------------------------------------
// Prep: W_c = m*W_v + (1-m)*W_r -> fp16, pre-swizzled chunk images.
// ---------------------------------------------------------------------------
__global__ void prep_kernel(const float* __restrict__ Wv, const float* __restrict__ Wr,
                            const float* __restrict__ mix) {
    int gid = blockIdx.x * blockDim.x + threadIdx.x;
    if (gid >= K_DIM * N_DIM) return;
    int n = gid & 511;
    int k = gid >> 9;
    float m = 1.0f / (1.0f + expf(-mix[0]));
    float w = m * Wv[k * N_DIM + n] + (1.0f - m) * Wr[k * N_DIM + n];
    int c  = k >> 6;
    int kk = k & 63;
    uint32_t off = swz((uint32_t)(n * 128 + kk * 2));
    *(__half*)(&g_Bimg[c][off]) = __float2half(w);
}

// ---------------------------------------------------------------------------
// Fused GEMM (fp16 mma.sync, 64x64 warp tiles) + relu + LayerNorm(512)
// ---------------------------------------------------------------------------
__global__ void __launch_bounds__(NT, 1)
gemm_ln_kernel(const float* __restrict__ x, const float* __restrict__ gamma,
               const float* __restrict__ beta, float* __restrict__ out) {
    extern __shared__ char smem[];
    const uint32_t sb = smem_u32(smem);
    const int tid  = threadIdx.x;
    const int wn   = tid >> 5;    // warp 0..7 -> 64-col slice, all 64 rows
    const int lane = tid & 31;

    const size_t m0 = (size_t)blockIdx.x * BM;

    // gamma/beta into smem
    {
        float* gsh = (float*)(smem + SM_GB);
        for (int i = tid; i < N_DIM; i += NT) {
            gsh[i]         = gamma[i];
            gsh[N_DIM + i] = beta[i];
        }
    }

    // ldmatrix base offsets
    const uint32_t arow = (uint32_t)((lane & 15) * 128 + (lane >> 4) * 16);   // + mt*2048 + ks*32
    const uint32_t brow = (uint32_t)((wn * 64 + ((lane >> 4) & 1) * 8 + (lane & 7)) * 128
                                     + ((lane >> 3) & 1) * 16);               // + bt*2048 + ks*32

    float acc[4][8][4];
    #pragma unroll
    for (int mt = 0; mt < 4; mt++)
        #pragma unroll
        for (int nt = 0; nt < 8; nt++)
            #pragma unroll
            for (int i = 0; i < 4; i++) acc[mt][nt][i] = 0.0f;

    // A: chunk = 64 rows x 64 f32 = 1024 float4; 4 per thread
    // idx = tid + i*NT: row = idx>>4 (0..63), seg = idx&15
    float4 av[4];
    #pragma unroll
    for (int i = 0; i < 4; i++) {
        int idx = tid + i * NT;
        av[i] = *(const float4*)(x + (m0 + (idx >> 4)) * K_DIM + (idx & 15) * 4);
    }

    // ---- prologue: B chunk0 cp.async, A chunk0 STS, A chunk1 LDG ----
    #pragma unroll
    for (int i = 0; i < 16; i++) {
        int j = tid + i * NT;              // 0..4095
        cp16(sb + SM_B + j * 16, &g_Bimg[0][j * 16]);
    }
    cp_commit();
    #pragma unroll
    for (int i = 0; i < 4; i++) {
        int idx = tid + i * NT;
        __half2 h01 = __floats2half2_rn(av[i].x, av[i].y);
        __half2 h23 = __floats2half2_rn(av[i].z, av[i].w);
        *(uint2*)(smem + SM_A + swz((uint32_t)((idx >> 4) * 128 + (idx & 15) * 8))) =
            make_uint2(*(uint32_t*)&h01, *(uint32_t*)&h23);
    }
    #pragma unroll
    for (int i = 0; i < 4; i++) {
        int idx = tid + i * NT;
        av[i] = *(const float4*)(x + (m0 + (idx >> 4)) * K_DIM + KC + (idx & 15) * 4);
    }

    #pragma unroll
    for (int c = 0; c < NCH; c++) {
        const int buf = c & 1;
        cp_wait0();
        __syncthreads();

        if (c < NCH - 1) {
            const int nbuf = buf ^ 1;
            // STS A chunk c+1
            #pragma unroll
            for (int i = 0; i < 4; i++) {
                int idx = tid + i * NT;
                __half2 h01 = __floats2half2_rn(av[i].x, av[i].y);
                __half2 h23 = __floats2half2_rn(av[i].z, av[i].w);
                *(uint2*)(smem + SM_A + nbuf * 8192 +
                          swz((uint32_t)((idx >> 4) * 128 + (idx & 15) * 8))) =
                    make_uint2(*(uint32_t*)&h01, *(uint32_t*)&h23);
            }
            // LDG A chunk c+2
            if (c < NCH - 2) {
                #pragma unroll
                for (int i = 0; i < 4; i++) {
                    int idx = tid + i * NT;
                    av[i] = *(const float4*)(x + (m0 + (idx >> 4)) * K_DIM
                                             + (c + 2) * KC + (idx & 15) * 4);
                }
            }
            // B chunk c+1 cp.async (overlaps MMA below)
            #pragma unroll
            for (int i = 0; i < 16; i++) {
                int j = tid + i * NT;
                cp16(sb + SM_B + nbuf * 65536 + j * 16, &g_Bimg[c + 1][j * 16]);
            }
            cp_commit();
        }

        // ---- MMA chunk c: 4 ks, A-fragment one-ks-ahead prefetch ----
        const uint32_t Ab = sb + SM_A + buf * 8192;
        const uint32_t Bb = sb + SM_B + buf * 65536;
        uint32_t af[2][4][4];
        #pragma unroll
        for (int mt = 0; mt < 4; mt++)
            ldsm4(af[0][mt], Ab + swz(arow + mt * 2048));
        #pragma unroll
        for (int ks = 0; ks < 4; ks++) {
            const int cur = ks & 1, nxt = cur ^ 1;
            if (ks < 3)
                #pragma unroll
                for (int mt = 0; mt < 4; mt++)
                    ldsm4(af[nxt][mt], Ab + swz(arow + mt * 2048 + (ks + 1) * 32));
            #pragma unroll
            for (int bt = 0; bt < 4; bt++) {
                uint32_t bh[4];
                ldsm4(bh, Bb + swz(brow + bt * 2048 + ks * 32));
                #pragma unroll
                for (int mt = 0; mt < 4; mt++) {
                    hmma(acc[mt][2 * bt],     af[cur][mt], &bh[0]);
                    hmma(acc[mt][2 * bt + 1], af[cur][mt], &bh[2]);
                }
            }
        }
    }

    // ------------------- Epilogue: relu + LayerNorm(512) -------------------
    float* psum  = (float*)(smem + SM_PS);   // [64][8]
    float* psq   = psum + 512;               // [64][8]
    float* stats = psq + 512;                // [64][2]

    #pragma unroll
    for (int mt = 0; mt < 4; mt++) {
        #pragma unroll
        for (int half = 0; half < 2; half++) {
            float s = 0.0f, q = 0.0f;
            #pragma unroll
            for (int nt = 0; nt < 8; nt++) {
                float v0 = fmaxf(acc[mt][nt][half * 2 + 0], 0.0f);
                float v1 = fmaxf(acc[mt][nt][half * 2 + 1], 0.0f);
                s += v0 + v1;
                q += v0 * v0 + v1 * v1;
            }
            s += __shfl_xor_sync(0xFFFFFFFFu, s, 1);
            q += __shfl_xor_sync(0xFFFFFFFFu, q, 1);
            s += __shfl_xor_sync(0xFFFFFFFFu, s, 2);
            q += __shfl_xor_sync(0xFFFFFFFFu, q, 2);
            if ((lane & 3) == 0) {
                int r = mt * 16 + (lane >> 2) + half * 8;   // 0..63
                psum[r * 8 + wn] = s;
                psq[r * 8 + wn]  = q;
            }
        }
    }
    __syncthreads();
    if (tid < BM) {
        float st = 0.0f, qt = 0.0f;
        #pragma unroll
        for (int i = 0; i < 8; i++) { st += psum[tid * 8 + i]; qt += psq[tid * 8 + i]; }
        float mean = st * (1.0f / 512.0f);
        float var  = qt * (1.0f / 512.0f) - mean * mean;
        stats[tid * 2]     = mean;
        stats[tid * 2 + 1] = rsqrtf(var + 1e-5f);
    }
    __syncthreads();

    const float* gsh = (const float*)(smem + SM_GB);
    const float* bsh = gsh + N_DIM;
    #pragma unroll
    for (int mt = 0; mt < 4; mt++) {
        #pragma unroll
        for (int half = 0; half < 2; half++) {
            int r = mt * 16 + (lane >> 2) + half * 8;
            float mean = stats[r * 2];
            float rstd = stats[r * 2 + 1];
            float* orow = out + (size_t)(m0 + r) * N_DIM;
            #pragma unroll
            for (int nt = 0; nt < 8; nt++) {
                int col = wn * 64 + nt * 8 + (lane & 3) * 2;
                float2 o;
                o.x = (fmaxf(acc[mt][nt][half * 2 + 0], 0.0f) - mean) * rstd * gsh[col]     + bsh[col];
                o.y = (fmaxf(acc[mt][nt][half * 2 + 1], 0.0f) - mean) * rstd * gsh[col + 1] + bsh[col + 1];
                *(float2*)(orow + col) = o;
            }
        }
    }
}

// ---------------------------------------------------------------------------
// Host launcher. Inputs: x, W_q, W_k, W_v, W_r, mix, gamma, beta
// ---------------------------------------------------------------------------
extern "C" void kernel_launch(void* const* d_in, const int* in_sizes, int n_in,
                              void* d_out, int out_size) {
    const float* x     = (const float*)d_in[0];
    const float* Wv    = (const float*)d_in[3];
    const float* Wr    = (const float*)d_in[4];
    const float* mix   = (const float*)d_in[5];
    const float* gamma = (const float*)d_in[6];
    const float* beta  = (const float*)d_in[7];
    float* out = (float*)d_out;

    cudaFuncSetAttribute(gemm_ln_kernel, cudaFuncAttributeMaxDynamicSharedMemorySize, SMEM_TOTAL);

    prep_kernel<<<(K_DIM * N_DIM + 255) / 256, 256>>>(Wv, Wr, mix);
    gemm_ln_kernel<<<M_TOT / BM, NT, SMEM_TOTAL>>>(x, gamma, beta, out);
}

// round 10
// speedup vs baseline: 1.0900x; 1.0134x over previous
#include <cuda_runtime.h>
#include <cuda_fp16.h>
#include <cstdint>

// ============================================================================
// out = LayerNorm(relu(x @ (m*W_v + (1-m)*W_r)))   [attention path is identity:
// softmax rows sum to 1 and the reference einsum contracts the softmax axis]
//   x: [131072, 256] f32,  W: [256, 512] f32,  out: [131072, 512] f32
// R10: persistent CTAs + CROSS-TILE software pipelining. B chunk images are
// tile-invariant, so the k-chunk stream is uniform across tiles: during tile
// t's last chunk we prefetch tile t+1's A/B; the epilogue overlaps next-tile
// loads and the per-tile prologue vanishes. B cp.async interleaved into MMA.
// fp16 mma.sync, 64x64 warp tiles, CTA = 64 rows x 512 cols, 8 warps.
// ============================================================================

static constexpr int K_DIM  = 256;
static constexpr int N_DIM  = 512;
static constexpr int BM     = 64;
static constexpr int KC     = 64;
static constexpr int NCH    = K_DIM / KC;   // 4
static constexpr int NTILES = 131072 / BM;  // 2048
static constexpr int NT     = 256;          // 8 warps; warp = 64 rows x 64 cols
static constexpr int GRID   = 148;          // persistent: 1 CTA/SM, 13-14 tiles each

// SMEM layout (bytes)
static constexpr int SM_B  = 0;            // 2 stages x 64 KB
static constexpr int SM_A  = 131072;       // 2 stages x 8 KB
static constexpr int SM_GB = 147456;       // gamma/beta f32 = 4 KB
static constexpr int SM_PS = 151552;       // psum[64][8]+psq[64][8]+stats[64][2]
static constexpr int SMEM_TOTAL = 156160;

// Pre-swizzled fp16 B chunk images: off(n,kk) = swz(n*128 + kk*2), kk = k%64.
__device__ __align__(16) unsigned char g_Bimg[NCH][65536];

// ---------------------------------------------------------------------------
__device__ __forceinline__ uint32_t smem_u32(const void* p) {
    uint32_t r;
    asm("{ .reg .u64 t; cvta.to.shared.u64 t, %1; cvt.u32.u64 %0, t; }" : "=r"(r) : "l"(p));
    return r;
}
__host__ __device__ __forceinline__ uint32_t swz(uint32_t o) { return o ^ ((o >> 3) & 0x70); }

__device__ __forceinline__ void cp16(uint32_t d, const void* s) {
    asm volatile("cp.async.cg.shared.global [%0], [%1], 16;" :: "r"(d), "l"(s));
}
__device__ __forceinline__ void cp_commit() { asm volatile("cp.async.commit_group;"); }
__device__ __forceinline__ void cp_wait0()  { asm volatile("cp.async.wait_group 0;"); }

__device__ __forceinline__ void ldsm4(uint32_t* r, uint32_t a) {
    asm volatile("ldmatrix.sync.aligned.m8n8.x4.shared.b16 {%0,%1,%2,%3}, [%4];"
                 : "=r"(r[0]), "=r"(r[1]), "=r"(r[2]), "=r"(r[3]) : "r"(a));
}
__device__ __forceinline__ void hmma(float* c, const uint32_t* a, const uint32_t* b) {
    asm volatile("mma.sync.aligned.m16n8k16.row.col.f32.f16.f16.f32 "
                 "{%0,%1,%2,%3},{%4,%5,%6,%7},{%8,%9},{%0,%1,%2,%3};"
                 : "+f"(c[0]), "+f"(c[1]), "+f"(c[2]), "+f"(c[3])
                 : "r"(a[0]), "r"(a[1]), "r"(a[2]), "r"(a[3]), "r"(b[0]), "r"(b[1]));
}

// ---------------------------------------------------------------------------
// Prep: W_c = m*W_v + (1-m)*W_r -> fp16, pre-swizzled chunk images.
// ---------------------------------------------------------------------------
__global__ void prep_kernel(const float* __restrict__ Wv, const float* __restrict__ Wr,
                            const float* __restrict__ mix) {
    int gid = blockIdx.x * blockDim.x + threadIdx.x;
    if (gid >= K_DIM * N_DIM) return;
    int n = gid & 511;
    int k = gid >> 9;
    float m = 1.0f / (1.0f + expf(-mix[0]));
    float w = m * Wv[k * N_DIM + n] + (1.0f - m) * Wr[k * N_DIM + n];
    int c  = k >> 6;
    int kk = k & 63;
    uint32_t off = swz((uint32_t)(n * 128 + kk * 2));
    *(__half*)(&g_Bimg[c][off]) = __float2half(w);
}

// ---------------------------------------------------------------------------
// Persistent fused GEMM (fp16 mma.sync) + relu + LayerNorm(512)
// ---------------------------------------------------------------------------
__global__ void __launch_bounds__(NT, 1)
gemm_ln_kernel(const float* __restrict__ x, const float* __restrict__ gamma,
               const float* __restrict__ beta, float* __restrict__ out) {
    extern __shared__ char smem[];
    const uint32_t sb = smem_u32(smem);
    const int tid  = threadIdx.x;
    const int wn   = tid >> 5;    // warp 0..7 -> 64-col slice, all 64 rows
    const int lane = tid & 31;
    const int bid  = blockIdx.x;

    // gamma/beta into smem (once)
    {
        float* gsh = (float*)(smem + SM_GB);
        for (int i = tid; i < N_DIM; i += NT) {
            gsh[i]         = gamma[i];
            gsh[N_DIM + i] = beta[i];
        }
    }

    // ldmatrix base offsets
    const uint32_t arow = (uint32_t)((lane & 15) * 128 + (lane >> 4) * 16);
    const uint32_t brow = (uint32_t)((wn * 64 + ((lane >> 4) & 1) * 8 + (lane & 7)) * 128
                                     + ((lane >> 3) & 1) * 16);

    // A indexing: chunk = 64 rows x 64 f32 = 1024 float4; 4 per thread
    int arowi[4], asegi[4];
    uint32_t asoff[4];
    #pragma unroll
    for (int i = 0; i < 4; i++) {
        int idx = tid + i * NT;
        arowi[i] = idx >> 4;
        asegi[i] = (idx & 15) * 4;
        asoff[i] = swz((uint32_t)((idx >> 4) * 128 + (idx & 15) * 8));
    }

    float* psum  = (float*)(smem + SM_PS);
    float* psq   = psum + 512;
    float* stats = psq + 512;
    const float* gsh = (const float*)(smem + SM_GB);
    const float* bsh = gsh + N_DIM;

    // ---- one-time prologue: B image0 -> buf0, A(tile0 chunk0) STS, chunk1 LDG ----
    float4 av[4];
    #pragma unroll
    for (int i = 0; i < 16; i++) {
        int j = tid + i * NT;
        cp16(sb + SM_B + j * 16, &g_Bimg[0][j * 16]);
    }
    cp_commit();
    {
        const size_t mb = (size_t)bid * BM;
        #pragma unroll
        for (int i = 0; i < 4; i++)
            av[i] = *(const float4*)(x + (mb + arowi[i]) * K_DIM + asegi[i]);
        #pragma unroll
        for (int i = 0; i < 4; i++) {
            __half2 h01 = __floats2half2_rn(av[i].x, av[i].y);
            __half2 h23 = __floats2half2_rn(av[i].z, av[i].w);
            *(uint2*)(smem + SM_A + asoff[i]) = make_uint2(*(uint32_t*)&h01, *(uint32_t*)&h23);
        }
        #pragma unroll
        for (int i = 0; i < 4; i++)
            av[i] = *(const float4*)(x + (mb + arowi[i]) * K_DIM + KC + asegi[i]);
    }

    for (int t = bid; t < NTILES; t += GRID) {
        const size_t m0 = (size_t)t * BM;
        const bool last_tile = (t + GRID >= NTILES);

        float acc[4][8][4];
        #pragma unroll
        for (int mt = 0; mt < 4; mt++)
            #pragma unroll
            for (int nt = 0; nt < 8; nt++)
                #pragma unroll
                for (int i = 0; i < 4; i++) acc[mt][nt][i] = 0.0f;

        #pragma unroll
        for (int c = 0; c < NCH; c++) {
            const int buf  = c & 1;
            const int nbuf = buf ^ 1;
            const bool has_next = !(last_tile && c == NCH - 1);

            cp_wait0();
            __syncthreads();

            // STS A for next chunk (this tile's c+1, or next tile's chunk0)
            if (has_next) {
                #pragma unroll
                for (int i = 0; i < 4; i++) {
                    __half2 h01 = __floats2half2_rn(av[i].x, av[i].y);
                    __half2 h23 = __floats2half2_rn(av[i].z, av[i].w);
                    *(uint2*)(smem + SM_A + nbuf * 8192 + asoff[i]) =
                        make_uint2(*(uint32_t*)&h01, *(uint32_t*)&h23);
                }
                // LDG A two chunks ahead: (t, c+2) or (t+GRID, c-2)
                if (c < NCH - 2) {
                    #pragma unroll
                    for (int i = 0; i < 4; i++)
                        av[i] = *(const float4*)(x + (m0 + arowi[i]) * K_DIM
                                                 + (c + 2) * KC + asegi[i]);
                } else if (!last_tile) {
                    const size_t mn = (size_t)(t + GRID) * BM;
                    #pragma unroll
                    for (int i = 0; i < 4; i++)
                        av[i] = *(const float4*)(x + (mn + arowi[i]) * K_DIM
                                                 + (c - 2) * KC + asegi[i]);
                }
            }

            // ---- MMA chunk c (B cp.async for next chunk interleaved per bt) ----
            const uint32_t Ab = sb + SM_A + buf * 8192;
            const uint32_t Bb = sb + SM_B + buf * 65536;
            const unsigned char* bimg = &g_Bimg[(c + 1) & 3][0];
            uint32_t af[2][4][4];
            #pragma unroll
            for (int mt = 0; mt < 4; mt++)
                ldsm4(af[0][mt], Ab + swz(arow + mt * 2048));
            #pragma unroll
            for (int ks = 0; ks < 4; ks++) {
                const int cur = ks & 1, nxt = cur ^ 1;
                if (ks < 3)
                    #pragma unroll
                    for (int mt = 0; mt < 4; mt++)
                        ldsm4(af[nxt][mt], Ab + swz(arow + mt * 2048 + (ks + 1) * 32));
                #pragma unroll
                for (int bt = 0; bt < 4; bt++) {
                    uint32_t bh[4];
                    ldsm4(bh, Bb + swz(brow + bt * 2048 + ks * 32));
                    // interleaved B prefetch: 1 cp16 per (ks,bt) -> 16 total
                    if (has_next) {
                        int j = tid + (ks * 4 + bt) * NT;
                        cp16(sb + SM_B + nbuf * 65536 + j * 16, bimg + j * 16);
                    }
                    #pragma unroll
                    for (int mt = 0; mt < 4; mt++) {
                        hmma(acc[mt][2 * bt],     af[cur][mt], &bh[0]);
                        hmma(acc[mt][2 * bt + 1], af[cur][mt], &bh[2]);
                    }
                }
            }
            cp_commit();
        }

        // ---------------- Epilogue: relu + LayerNorm(512) ----------------
        // (next tile's B image0 + A chunk0 already in flight / in smem)
        #pragma unroll
        for (int mt = 0; mt < 4; mt++) {
            #pragma unroll
            for (int half = 0; half < 2; half++) {
                float s = 0.0f, q = 0.0f;
                #pragma unroll
                for (int nt = 0; nt < 8; nt++) {
                    float v0 = fmaxf(acc[mt][nt][half * 2 + 0], 0.0f);
                    float v1 = fmaxf(acc[mt][nt][half * 2 + 1], 0.0f);
                    s += v0 + v1;
                    q += v0 * v0 + v1 * v1;
                }
                s += __shfl_xor_sync(0xFFFFFFFFu, s, 1);
                q += __shfl_xor_sync(0xFFFFFFFFu, q, 1);
                s += __shfl_xor_sync(0xFFFFFFFFu, s, 2);
                q += __shfl_xor_sync(0xFFFFFFFFu, q, 2);
                if ((lane & 3) == 0) {
                    int r = mt * 16 + (lane >> 2) + half * 8;
                    psum[r * 8 + wn] = s;
                    psq[r * 8 + wn]  = q;
                }
            }
        }
        __syncthreads();
        if (tid < BM) {
            float st = 0.0f, qt = 0.0f;
            #pragma unroll
            for (int i = 0; i < 8; i++) { st += psum[tid * 8 + i]; qt += psq[tid * 8 + i]; }
            float mean = st * (1.0f / 512.0f);
            float var  = qt * (1.0f / 512.0f) - mean * mean;
            stats[tid * 2]     = mean;
            stats[tid * 2 + 1] = rsqrtf(var + 1e-5f);
        }
        __syncthreads();

        #pragma unroll
        for (int mt = 0; mt < 4; mt++) {
            #pragma unroll
            for (int half = 0; half < 2; half++) {
                int r = mt * 16 + (lane >> 2) + half * 8;
                float mean = stats[r * 2];
                float rstd = stats[r * 2 + 1];
                float* orow = out + (size_t)(m0 + r) * N_DIM;
                #pragma unroll
                for (int nt = 0; nt < 8; nt++) {
                    int col = wn * 64 + nt * 8 + (lane & 3) * 2;
                    float2 o;
                    o.x = (fmaxf(acc[mt][nt][half * 2 + 0], 0.0f) - mean) * rstd * gsh[col]     + bsh[col];
                    o.y = (fmaxf(acc[mt][nt][half * 2 + 1], 0.0f) - mean) * rstd * gsh[col + 1] + bsh[col + 1];
                    *(float2*)(orow + col) = o;
                }
            }
        }
        __syncthreads();   // psum/stats reuse next tile; A/B buffers protected by chunk waits
    }
}

// ---------------------------------------------------------------------------
// Host launcher. Inputs: x, W_q, W_k, W_v, W_r, mix, gamma, beta
// ---------------------------------------------------------------------------
extern "C" void kernel_launch(void* const* d_in, const int* in_sizes, int n_in,
                              void* d_out, int out_size) {
    const float* x     = (const float*)d_in[0];
    const float* Wv    = (const float*)d_in[3];
    const float* Wr    = (const float*)d_in[4];
    const float* mix   = (const float*)d_in[5];
    const float* gamma = (const float*)d_in[6];
    const float* beta  = (const float*)d_in[7];
    float* out = (float*)d_out;

    cudaFuncSetAttribute(gemm_ln_kernel, cudaFuncAttributeMaxDynamicSharedMemorySize, SMEM_TOTAL);

    prep_kernel<<<(K_DIM * N_DIM + 255) / 256, 256>>>(Wv, Wr, mix);
    gemm_ln_kernel<<<GRID, NT, SMEM_TOTAL>>>(x, gamma, beta, out);
}